// round 14
// baseline (speedup 1.0000x reference)
#include <cuda_runtime.h>
#include <cstdint>

#define SAMPLE 8192
#define KNN 8
#define WPB 8            // query-warps per block
#define CAP 16           // survivor slots per (warp, lane)
#define SUB 512          // threshold subsample size (x-local, contiguous)
#define NB 512           // x-buckets over [-4, 4]
#define EPSV 1e-12f
#define SENT 0x7F800000FFFFFFFFull
#define FINF __int_as_float(0x7f800000)

// g_P: (x, y, z, |p|^2) per gathered point.  g_S: gathered sh0.
// g_C: x-bucket-sorted candidates in Q-form (-2x, -2y, -2z, |p|^2).
// g_CI: original gathered index per sorted slot.  g_boff: bucket offsets.
__device__ float4 g_P[SAMPLE];
__device__ float4 g_S[SAMPLE];
__device__ float4 g_C[SAMPLE];
__device__ unsigned short g_CI[SAMPLE];
__device__ unsigned g_boff[NB + 1];
__device__ unsigned g_bcnt[NB];
__device__ unsigned g_cur[NB];

// Clamped bucketing is monotone non-decreasing in x, which is all the window
// logic needs (points sorted by bucket; window = contiguous bucket span).
__device__ __forceinline__ int bucket_of(float x) {
    int b = (int)((x + 4.f) * (NB / 8.f));
    return min(NB - 1, max(0, b));
}

__global__ void gather_kernel(const float* __restrict__ means,
                              const float* __restrict__ sh0,
                              const int* __restrict__ idx_raw) {
    int i = blockIdx.x * blockDim.x + threadIdx.x;
    if (i >= SAMPLE) return;
    // int64 vs int32 index detection: little-endian int64 < 2^31 has all odd
    // words zero.
    bool is64 = ((idx_raw[1] | idx_raw[3] | idx_raw[5] | idx_raw[7] |
                  idx_raw[9] | idx_raw[11] | idx_raw[13] | idx_raw[15]) == 0);
    long long j = is64 ? ((const long long*)idx_raw)[i] : (long long)idx_raw[i];
    float x = means[3 * j + 0];
    float y = means[3 * j + 1];
    float z = means[3 * j + 2];
    float sq = fmaf(z, z, fmaf(y, y, x * x));
    g_P[i] = make_float4(x, y, z, sq);
    g_S[i] = make_float4(sh0[3 * j + 0], sh0[3 * j + 1], sh0[3 * j + 2], 0.f);
    atomicAdd(&g_bcnt[bucket_of(x)], 1u);
}

// One block: exclusive prefix scan of the NB=512 bucket counts.
__global__ void __launch_bounds__(NB) scan_kernel() {
    __shared__ unsigned wsum[NB / 32];
    const int tid = threadIdx.x;
    const int lane = tid & 31;
    unsigned v = g_bcnt[tid];
    unsigned x = v;
#pragma unroll
    for (int o = 1; o < 32; o <<= 1) {
        unsigned y = __shfl_up_sync(0xFFFFFFFFu, x, o);
        if (lane >= o) x += y;
    }
    if (lane == 31) wsum[tid >> 5] = x;
    __syncthreads();
    if (tid < NB / 32) {
        unsigned w = wsum[tid], s = w;
#pragma unroll
        for (int o = 1; o < NB / 32; o <<= 1) {
            unsigned y = __shfl_up_sync(0xFFFFu, s, o);
            if (tid >= o) s += y;
        }
        wsum[tid] = s - w;  // exclusive across warps
    }
    __syncthreads();
    unsigned off = x - v + wsum[tid >> 5];
    g_boff[tid] = off;
    g_cur[tid] = off;
    if (tid == 0) g_boff[NB] = SAMPLE;
}

__global__ void scatter_kernel() {
    int i = blockIdx.x * blockDim.x + threadIdx.x;
    if (i >= SAMPLE) return;
    float4 p = g_P[i];
    unsigned pos = atomicAdd(&g_cur[bucket_of(p.x)], 1u);
    g_C[pos] = make_float4(-2.f * p.x, -2.f * p.y, -2.f * p.z, p.w);
    g_CI[pos] = (unsigned short)i;
}

__device__ __forceinline__ void insert9(unsigned long long heap[9],
                                        unsigned long long key) {
    unsigned long long cur = key;  // flat if-converted insert (cold path)
#pragma unroll
    for (int k = 0; k < 9; k++) {
        unsigned long long h = heap[k];
        bool lt = cur < h;
        heap[k] = lt ? cur : h;
        cur = lt ? h : cur;
    }
}

// One warp per query; scans only the x-window of the sorted candidate array.
__global__ void __launch_bounds__(32 * WPB) knn_loss_kernel(
    float* __restrict__ out) {
    __shared__ unsigned short buf[WPB][CAP][32];

    const int lane = threadIdx.x & 31;
    const int warp = threadIdx.x >> 5;
    const int i = blockIdx.x * WPB + warp;
    const float4 pi = g_P[i];

    // ---- Phase 1: T = 9th-smallest clamped d2 over the 512 sorted
    // candidates x-nearest to the query (contiguous slice centered on the
    // query's bucket offset). Any subset's 9th order stat >= the true 9th-NN
    // d2, and x-local subsets make T nearly tight. Per-lane min + 9 knockout
    // rounds; ties knock out together (T only loosens, stays valid).
    int start = (int)g_boff[bucket_of(pi.x)] - SUB / 2;
    start = min(SAMPLE - SUB, max(0, start));
    float mmin = FINF;
#pragma unroll
    for (int u = 0; u < SUB / 32; u++) {
        float4 c = g_C[start + u * 32 + lane];
        float d = c.w + pi.w;
        d = fmaf(c.x, pi.x, d);
        d = fmaf(c.y, pi.y, d);
        d = fmaf(c.z, pi.z, d);
        mmin = fminf(mmin, fmaxf(d, EPSV));
    }
    float T = FINF;
    {
        float m = mmin;
#pragma unroll
        for (int r = 0; r < 9; r++) {
            float t = m;
#pragma unroll
            for (int o = 16; o > 0; o >>= 1)
                t = fminf(t, __shfl_xor_sync(0xFFFFFFFFu, t, o));
            if (m == t) m = FINF;
            if (r == 8) T = t;
        }
    }

    // ---- Window: if (x_j - x_i)^2 > T then d2 > T, and >=9 candidates have
    // d2c <= T, so such j can never enter the top-9. Whole-bucket inclusion
    // plus an ulp guard keeps pruning strictly conservative.
    const float s = sqrtf(T) * 1.0000024f;
    const unsigned lo = g_boff[bucket_of(pi.x - s)];
    const unsigned hi = g_boff[bucket_of(pi.x + s) + 1];

    // ---- Phase 2: scan the window; predicated lane-private survivor stores.
    // Unroll 2 for memory-level parallelism (2 independent LDG.128 in
    // flight); second element predicated off at the ragged end.
    int cnt = 0;
    for (unsigned p = lo + lane; p < hi; p += 64) {
        unsigned p2 = p + 32;
        float4 c = g_C[p];
        float4 c2;
        bool has2 = p2 < hi;
        if (has2) c2 = g_C[p2];
        float d = c.w + pi.w;
        d = fmaf(c.x, pi.x, d);
        d = fmaf(c.y, pi.y, d);
        d = fmaf(c.z, pi.z, d);
        bool a = d <= T;  // raw <= clamped: never false-rejects
        bool st = a & (cnt < CAP);
        if (st) buf[warp][cnt][lane] = (unsigned short)p;
        cnt += a;
        if (has2) {
            float e = c2.w + pi.w;
            e = fmaf(c2.x, pi.x, e);
            e = fmaf(c2.y, pi.y, e);
            e = fmaf(c2.z, pi.z, e);
            bool a2 = e <= T;
            bool st2 = a2 & (cnt < CAP);
            if (st2) buf[warp][cnt][lane] = (unsigned short)p2;
            cnt += a2;
        }
    }

    // ---- Phase 3: exact (d2, orig_j)-keyed top-9 over survivors.
    unsigned long long heap[9];
#pragma unroll
    for (int k = 0; k < 9; k++) heap[k] = SENT;
    int n = min(cnt, CAP);
    for (int ss = 0; ss < n; ss++) {
        unsigned p = buf[warp][ss][lane];
        float4 c = g_C[p];
        float d = c.w + pi.w;
        d = fmaf(c.x, pi.x, d);
        d = fmaf(c.y, pi.y, d);
        d = fmaf(c.z, pi.z, d);
        float d2c = fmaxf(d, EPSV);
        unsigned j = g_CI[p];
        insert9(heap, ((unsigned long long)__float_as_uint(d2c) << 32) | j);
    }
    __syncwarp();

    // Warp pop-merge; real keys unique (distinct orig j) -> one pop/round.
    unsigned long long mykey = SENT;
#pragma unroll
    for (int r = 0; r < 9; r++) {
        unsigned long long cand = heap[0];
        unsigned long long m = cand;
#pragma unroll
        for (int o = 16; o > 0; o >>= 1) {
            unsigned long long other = __shfl_xor_sync(0xFFFFFFFFu, m, o);
            m = (other < m) ? other : m;
        }
        if (cand == m) {
#pragma unroll
            for (int k = 0; k < 8; k++) heap[k] = heap[k + 1];
            heap[8] = SENT;
        }
        if (lane == r) mykey = m;
    }

    // Ranks 1..8 (rank 0 = self/dup, dropped like knn_idx[:, 1:]).
    float acc = 0.f;
    if (lane >= 1 && lane <= KNN) {
        int j = (int)(mykey & (unsigned)(SAMPLE - 1));
        float d2 = __uint_as_float((unsigned)(mykey >> 32));
        float w = __expf(-sqrtf(d2));
        float4 si = g_S[i];
        float4 sj = g_S[j];
        float dx = si.x - sj.x, dy = si.y - sj.y, dz = si.z - sj.z;
        acc = w * (dx * dx + dy * dy + dz * dz);
    }
#pragma unroll
    for (int o = 16; o > 0; o >>= 1)
        acc += __shfl_xor_sync(0xFFFFFFFFu, acc, o);
    if (lane == 0)
        atomicAdd(out, acc * (1.f / (float)(SAMPLE * KNN * 3)));
}

extern "C" void kernel_launch(void* const* d_in, const int* in_sizes, int n_in,
                              void* d_out, int out_size) {
    const float* means = (const float*)d_in[0];
    const float* sh0 = (const float*)d_in[1];
    const int* idx = (const int*)d_in[2];
    float* out = (float*)d_out;

    // Zero the scalar output and the bucket counters via memset nodes
    // (graph-capturable; no kernel launch latency).
    void* bcnt_ptr = nullptr;
    cudaGetSymbolAddress(&bcnt_ptr, g_bcnt);
    cudaMemsetAsync(out, 0, sizeof(float), 0);
    cudaMemsetAsync(bcnt_ptr, 0, NB * sizeof(unsigned), 0);

    gather_kernel<<<64, 128>>>(means, sh0, idx);
    scan_kernel<<<1, NB>>>();
    scatter_kernel<<<64, 128>>>();
    knn_loss_kernel<<<SAMPLE / WPB, 32 * WPB>>>(out);
}

// round 15
// speedup vs baseline: 1.1382x; 1.1382x over previous
#include <cuda_runtime.h>
#include <cstdint>

#define SAMPLE 8192
#define KNN 8
#define WPB 8            // query-warps per block
#define CAP 16           // survivor slots per (warp, lane)
#define SUB 512          // threshold subsample size (x-local, contiguous)
#define NB 512           // x-buckets over [-4, 4]
#define EPSV 1e-12f
#define SENT 0x7F800000FFFFFFFFull
#define FINF __int_as_float(0x7f800000)

// g_P: (x, y, z, |p|^2) per gathered point.  g_S: gathered sh0.
// g_C: x-bucket-sorted candidates in Q-form (-2x, -2y, -2z, |p|^2).
// g_CI: original gathered index per sorted slot.  g_boff: bucket offsets.
__device__ float4 g_P[SAMPLE];
__device__ float4 g_S[SAMPLE];
__device__ float4 g_C[SAMPLE];
__device__ unsigned short g_CI[SAMPLE];
__device__ unsigned g_boff[NB + 1];
__device__ unsigned g_bcnt[NB];
__device__ unsigned g_cur[NB];

// Clamped bucketing is monotone non-decreasing in x, which is all the window
// logic needs (points sorted by bucket; window = contiguous bucket span).
__device__ __forceinline__ int bucket_of(float x) {
    int b = (int)((x + 4.f) * (NB / 8.f));
    return min(NB - 1, max(0, b));
}

__global__ void gather_kernel(const float* __restrict__ means,
                              const float* __restrict__ sh0,
                              const int* __restrict__ idx_raw) {
    int i = blockIdx.x * blockDim.x + threadIdx.x;
    if (i >= SAMPLE) return;
    // int64 vs int32 index detection: little-endian int64 < 2^31 has all odd
    // words zero.
    bool is64 = ((idx_raw[1] | idx_raw[3] | idx_raw[5] | idx_raw[7] |
                  idx_raw[9] | idx_raw[11] | idx_raw[13] | idx_raw[15]) == 0);
    long long j = is64 ? ((const long long*)idx_raw)[i] : (long long)idx_raw[i];
    float x = means[3 * j + 0];
    float y = means[3 * j + 1];
    float z = means[3 * j + 2];
    float sq = fmaf(z, z, fmaf(y, y, x * x));
    g_P[i] = make_float4(x, y, z, sq);
    g_S[i] = make_float4(sh0[3 * j + 0], sh0[3 * j + 1], sh0[3 * j + 2], 0.f);
    atomicAdd(&g_bcnt[bucket_of(x)], 1u);
}

// One block: exclusive prefix scan of the NB=512 bucket counts.
__global__ void __launch_bounds__(NB) scan_kernel() {
    __shared__ unsigned wsum[NB / 32];
    const int tid = threadIdx.x;
    const int lane = tid & 31;
    unsigned v = g_bcnt[tid];
    unsigned x = v;
#pragma unroll
    for (int o = 1; o < 32; o <<= 1) {
        unsigned y = __shfl_up_sync(0xFFFFFFFFu, x, o);
        if (lane >= o) x += y;
    }
    if (lane == 31) wsum[tid >> 5] = x;
    __syncthreads();
    if (tid < NB / 32) {
        unsigned w = wsum[tid], s = w;
#pragma unroll
        for (int o = 1; o < NB / 32; o <<= 1) {
            unsigned y = __shfl_up_sync(0xFFFFu, s, o);
            if (tid >= o) s += y;
        }
        wsum[tid] = s - w;  // exclusive across warps
    }
    __syncthreads();
    unsigned off = x - v + wsum[tid >> 5];
    g_boff[tid] = off;
    g_cur[tid] = off;
    if (tid == 0) g_boff[NB] = SAMPLE;
}

__global__ void scatter_kernel() {
    int i = blockIdx.x * blockDim.x + threadIdx.x;
    if (i >= SAMPLE) return;
    float4 p = g_P[i];
    unsigned pos = atomicAdd(&g_cur[bucket_of(p.x)], 1u);
    g_C[pos] = make_float4(-2.f * p.x, -2.f * p.y, -2.f * p.z, p.w);
    g_CI[pos] = (unsigned short)i;
}

__device__ __forceinline__ void insert9(unsigned long long heap[9],
                                        unsigned long long key) {
    unsigned long long cur = key;  // flat if-converted insert (cold path)
#pragma unroll
    for (int k = 0; k < 9; k++) {
        unsigned long long h = heap[k];
        bool lt = cur < h;
        heap[k] = lt ? cur : h;
        cur = lt ? h : cur;
    }
}

// One warp per SORTED slot: warp at slot i processes original query g_CI[i].
// Sorted-order processing makes the 8 warps of a block share nearly identical
// x-windows (L1 reuse) and uniform work. Bijection -> every query done once;
// the final sum is order-independent.
__global__ void __launch_bounds__(32 * WPB) knn_loss_kernel(
    float* __restrict__ out) {
    __shared__ unsigned short buf[WPB][CAP][32];

    const int lane = threadIdx.x & 31;
    const int warp = threadIdx.x >> 5;
    const int slot = blockIdx.x * WPB + warp;  // sorted position
    const int i = g_CI[slot];                  // original query index
    const float4 pi = g_P[i];

    // ---- Phase 1: T = 9th-smallest clamped d2 over the 512 sorted
    // candidates centered on the query's own sorted slot. Any subset's 9th
    // order stat >= the true 9th-NN d2; centering makes it nearly tight.
    // Per-lane min + 9 knockout rounds; ties knock out together (T only
    // loosens, stays valid).
    int start = min(SAMPLE - SUB, max(0, slot - SUB / 2));
    float mmin = FINF;
#pragma unroll
    for (int u = 0; u < SUB / 32; u++) {
        float4 c = g_C[start + u * 32 + lane];
        float d = c.w + pi.w;
        d = fmaf(c.x, pi.x, d);
        d = fmaf(c.y, pi.y, d);
        d = fmaf(c.z, pi.z, d);
        mmin = fminf(mmin, fmaxf(d, EPSV));
    }
    float T = FINF;
    {
        float m = mmin;
#pragma unroll
        for (int r = 0; r < 9; r++) {
            float t = m;
#pragma unroll
            for (int o = 16; o > 0; o >>= 1)
                t = fminf(t, __shfl_xor_sync(0xFFFFFFFFu, t, o));
            if (m == t) m = FINF;
            if (r == 8) T = t;
        }
    }

    // ---- Window: if (x_j - x_i)^2 > T then d2 > T, and >=9 candidates have
    // d2c <= T, so such j can never enter the top-9. Whole-bucket inclusion
    // plus an ulp guard keeps pruning strictly conservative.
    const float s = sqrtf(T) * 1.0000024f;
    const unsigned lo = g_boff[bucket_of(pi.x - s)];
    const unsigned hi = g_boff[bucket_of(pi.x + s) + 1];

    // ---- Phase 2: scan the window; predicated lane-private survivor stores.
    int cnt = 0;
    for (unsigned p = lo + lane; p < hi; p += 32) {
        float4 c = g_C[p];
        float d = c.w + pi.w;
        d = fmaf(c.x, pi.x, d);
        d = fmaf(c.y, pi.y, d);
        d = fmaf(c.z, pi.z, d);
        bool a = d <= T;  // raw <= clamped: never false-rejects
        bool st = a & (cnt < CAP);
        if (st) buf[warp][cnt][lane] = (unsigned short)p;
        cnt += a;
    }

    // ---- Phase 3: exact (d2, orig_j)-keyed top-9 over survivors.
    unsigned long long heap[9];
#pragma unroll
    for (int k = 0; k < 9; k++) heap[k] = SENT;
    int n = min(cnt, CAP);
    for (int ss = 0; ss < n; ss++) {
        unsigned p = buf[warp][ss][lane];
        float4 c = g_C[p];
        float d = c.w + pi.w;
        d = fmaf(c.x, pi.x, d);
        d = fmaf(c.y, pi.y, d);
        d = fmaf(c.z, pi.z, d);
        float d2c = fmaxf(d, EPSV);
        unsigned j = g_CI[p];
        insert9(heap, ((unsigned long long)__float_as_uint(d2c) << 32) | j);
    }
    __syncwarp();

    // Warp pop-merge; real keys unique (distinct orig j) -> one pop/round.
    unsigned long long mykey = SENT;
#pragma unroll
    for (int r = 0; r < 9; r++) {
        unsigned long long cand = heap[0];
        unsigned long long m = cand;
#pragma unroll
        for (int o = 16; o > 0; o >>= 1) {
            unsigned long long other = __shfl_xor_sync(0xFFFFFFFFu, m, o);
            m = (other < m) ? other : m;
        }
        if (cand == m) {
#pragma unroll
            for (int k = 0; k < 8; k++) heap[k] = heap[k + 1];
            heap[8] = SENT;
        }
        if (lane == r) mykey = m;
    }

    // Ranks 1..8 (rank 0 = self/dup, dropped like knn_idx[:, 1:]).
    float acc = 0.f;
    if (lane >= 1 && lane <= KNN) {
        int j = (int)(mykey & (unsigned)(SAMPLE - 1));
        float d2 = __uint_as_float((unsigned)(mykey >> 32));
        float w = __expf(-sqrtf(d2));
        float4 si = g_S[i];
        float4 sj = g_S[j];
        float dx = si.x - sj.x, dy = si.y - sj.y, dz = si.z - sj.z;
        acc = w * (dx * dx + dy * dy + dz * dz);
    }
#pragma unroll
    for (int o = 16; o > 0; o >>= 1)
        acc += __shfl_xor_sync(0xFFFFFFFFu, acc, o);
    if (lane == 0)
        atomicAdd(out, acc * (1.f / (float)(SAMPLE * KNN * 3)));
}

extern "C" void kernel_launch(void* const* d_in, const int* in_sizes, int n_in,
                              void* d_out, int out_size) {
    const float* means = (const float*)d_in[0];
    const float* sh0 = (const float*)d_in[1];
    const int* idx = (const int*)d_in[2];
    float* out = (float*)d_out;

    // Zero the scalar output and the bucket counters via memset nodes
    // (graph-capturable; no kernel launch latency).
    void* bcnt_ptr = nullptr;
    cudaGetSymbolAddress(&bcnt_ptr, g_bcnt);
    cudaMemsetAsync(out, 0, sizeof(float), 0);
    cudaMemsetAsync(bcnt_ptr, 0, NB * sizeof(unsigned), 0);

    gather_kernel<<<64, 128>>>(means, sh0, idx);
    scan_kernel<<<1, NB>>>();
    scatter_kernel<<<64, 128>>>();
    knn_loss_kernel<<<SAMPLE / WPB, 32 * WPB>>>(out);
}